// round 1
// baseline (speedup 1.0000x reference)
#include <cuda_runtime.h>
#include <cstdint>

// Problem constants (fixed by the dataset)
#define BDIM   256      // IN_DIM
#define BMAX   131072   // B
// qW: [B, 2*256], wn: [B, 2*256]

// ---- scratch (static device globals; no dynamic allocation allowed) ----
__device__ float g_wbig[256 * 640];             // fused K1 weight [k=256][n=640]: P0|P1|Wco^T
__device__ float g_mcatT[512 * 128];            // fused K3 weight [i=512][j=128]
__device__ float g_qw[(size_t)BMAX * 512];      // qW per batch row (head0 256 | head1 256)
__device__ float g_wn[(size_t)BMAX * 512];      // attn-weighted neighbor sums

// ============================================================
// K0a: Wbig[k][n]  n<512: P_h[k][j] = sum_a Wc[h*64+a][k]*Wn[h*64+a][j]
//                  n>=512: W_center_out[n-512][k]
// ============================================================
__global__ void k_prep_wbig(const float* __restrict__ Wc,
                            const float* __restrict__ Wn,
                            const float* __restrict__ Wco) {
    int idx = blockIdx.x * 256 + threadIdx.x;
    if (idx >= 256 * 640) return;
    int kk = idx / 640;
    int n  = idx % 640;
    float val;
    if (n < 512) {
        int h = n >> 8;
        int j = n & 255;
        float s = 0.f;
#pragma unroll 8
        for (int a = 0; a < 64; a++)
            s = fmaf(Wc[(h * 64 + a) * 256 + kk], Wn[(h * 64 + a) * 256 + j], s);
        val = s;
    } else {
        val = Wco[(n - 512) * 256 + kk];
    }
    g_wbig[kk * 640 + n] = val;
}

// ============================================================
// K0b: McatT[i][j], i = h*256+ii:  sum_d W_out[j][h*128+d] * W_value[h*128+d][ii]
// ============================================================
__global__ void k_prep_mcat(const float* __restrict__ Wo,
                            const float* __restrict__ Wv) {
    int idx = blockIdx.x * 256 + threadIdx.x;
    if (idx >= 512 * 128) return;
    int i = idx >> 7;
    int j = idx & 127;
    int h  = i >> 8;
    int ii = i & 255;
    float s = 0.f;
#pragma unroll 8
    for (int d = 0; d < 128; d++)
        s = fmaf(Wo[j * 256 + h * 128 + d], Wv[(h * 128 + d) * 256 + ii], s);
    g_mcatT[i * 128 + j] = s;
}

// ============================================================
// Tiled fp32 SGEMM: C[M,N] = A[M,KD] * B[KD,N]
// BM=BN=128, BK=16, 256 threads, 8x8 per thread.
// MODE 0: A=center (param), B=g_wbig (N=640). cols<512 -> g_qw, cols>=512 -> dOut[:,0:128]
// MODE 1: A=g_wn,            B=g_mcatT (N=128). cols -> dOut[:,128:256]
// ============================================================
template <int KD, int LDB, int MODE>
__global__ __launch_bounds__(256) void k_sgemm(const float* __restrict__ Ain,
                                               float* __restrict__ dOut) {
    __shared__ float As[16][132];   // transposed A tile, padded
    __shared__ float Bs[16][128];

    const float* A  = (MODE == 0) ? Ain : g_wn;
    const float* Bm = (MODE == 0) ? g_wbig : g_mcatT;

    const int tid = threadIdx.x;
    const int bm = blockIdx.x, bn = blockIdx.y;
    const int tx = tid & 15, ty = tid >> 4;

    const float* Ab = A + (size_t)bm * 128 * KD;
    const float* Bb = Bm + bn * 128;

    float acc[8][8];
#pragma unroll
    for (int i = 0; i < 8; i++)
#pragma unroll
        for (int j = 0; j < 8; j++) acc[i][j] = 0.f;

    for (int k0 = 0; k0 < KD; k0 += 16) {
        // load A tile (128x16), store transposed
#pragma unroll
        for (int r = 0; r < 2; r++) {
            int v = tid + 256 * r;          // 0..511
            int row = v >> 2, c4 = v & 3;
            float4 x = *(const float4*)(Ab + (size_t)row * KD + k0 + c4 * 4);
            As[c4 * 4 + 0][row] = x.x;
            As[c4 * 4 + 1][row] = x.y;
            As[c4 * 4 + 2][row] = x.z;
            As[c4 * 4 + 3][row] = x.w;
        }
        // load B tile (16x128)
#pragma unroll
        for (int r = 0; r < 2; r++) {
            int v = tid + 256 * r;          // 0..511
            int kk = v >> 5, c4 = v & 31;
            *(float4*)(&Bs[kk][c4 * 4]) =
                *(const float4*)(Bb + (size_t)(k0 + kk) * LDB + c4 * 4);
        }
        __syncthreads();

#pragma unroll
        for (int kk = 0; kk < 16; kk++) {
            float4 a0 = *(const float4*)&As[kk][ty * 8];
            float4 a1 = *(const float4*)&As[kk][ty * 8 + 4];
            float4 b0 = *(const float4*)&Bs[kk][tx * 8];
            float4 b1 = *(const float4*)&Bs[kk][tx * 8 + 4];
            float ra[8] = {a0.x, a0.y, a0.z, a0.w, a1.x, a1.y, a1.z, a1.w};
            float rb[8] = {b0.x, b0.y, b0.z, b0.w, b1.x, b1.y, b1.z, b1.w};
#pragma unroll
            for (int i = 0; i < 8; i++)
#pragma unroll
                for (int j = 0; j < 8; j++)
                    acc[i][j] = fmaf(ra[i], rb[j], acc[i][j]);
        }
        __syncthreads();
    }

    const int row0 = bm * 128 + ty * 8;
    const int col0 = bn * 128 + tx * 8;
#pragma unroll
    for (int i = 0; i < 8; i++) {
        int row = row0 + i;
#pragma unroll
        for (int j4 = 0; j4 < 8; j4 += 4) {
            float4 v = make_float4(acc[i][j4], acc[i][j4 + 1],
                                   acc[i][j4 + 2], acc[i][j4 + 3]);
            int col = col0 + j4;
            if (MODE == 0) {
                if (col < 512)
                    *(float4*)(g_qw + (size_t)row * 512 + col) = v;
                else
                    *(float4*)(dOut + (size_t)row * 256 + (col - 512)) = v;
            } else {
                *(float4*)(dOut + (size_t)row * 256 + 128 + col) = v;
            }
        }
    }
}

// ============================================================
// K2: per-batch attention. Block = one b, 128 threads.
// scores[h][k] = 0.125*dot(nb[k], qW[h]) + ew[k]; softmax over k;
// wn[h][c] = sum_k attn[h][k]*nb[k][c]
// ============================================================
__global__ __launch_bounds__(128) void k_attn(const float* __restrict__ nb_g,
                                              const float* __restrict__ ew_g) {
    const int b = blockIdx.x;
    __shared__ float nb[16 * 260];   // padded stride 260 floats (16B aligned)
    __shared__ float qw[512];
    __shared__ float sc[2][16];
    __shared__ float at[2][16];

    const int tid = threadIdx.x;

    // stage neighbors (16x256 fp32 = 16KB) + qW (2KB)
    const float4* src = (const float4*)(nb_g + (size_t)b * 4096);
#pragma unroll
    for (int r = 0; r < 8; r++) {
        int v = tid + 128 * r;           // 0..1023 float4s
        int k = v >> 6, c4 = v & 63;
        float4 x = src[v];
        *(float4*)&nb[k * 260 + c4 * 4] = x;
    }
    const float4* qsrc = (const float4*)(g_qw + (size_t)b * 512);
    *(float4*)&qw[tid * 4] = qsrc[tid];
    __syncthreads();

    // scores: 32 dots of length 256, 4 threads per dot
    {
        int pair = tid >> 2, sub = tid & 3;
        int h = pair >> 4, k = pair & 15;
        const float* nrow = &nb[k * 260 + sub * 64];
        const float* qrow = &qw[h * 256 + sub * 64];
        float s = 0.f;
#pragma unroll
        for (int c = 0; c < 64; c++) s = fmaf(nrow[c], qrow[c], s);
        s += __shfl_xor_sync(0xffffffffu, s, 1);
        s += __shfl_xor_sync(0xffffffffu, s, 2);
        if (sub == 0)
            sc[h][k] = s * 0.125f + ew_g[(size_t)b * 16 + k];
    }
    __syncthreads();

    // softmax over k (16) per head — warp 0 handles both heads
    if (tid < 32) {
        int hh = tid >> 4, kk = tid & 15;
        float v = sc[hh][kk];
        float m = v;
#pragma unroll
        for (int o = 8; o >= 1; o >>= 1)
            m = fmaxf(m, __shfl_xor_sync(0xffffffffu, m, o));
        float e = __expf(v - m);
        float sum = e;
#pragma unroll
        for (int o = 8; o >= 1; o >>= 1)
            sum += __shfl_xor_sync(0xffffffffu, sum, o);
        at[hh][kk] = e / sum;
    }
    __syncthreads();

    // wn[h][c]
#pragma unroll
    for (int r = 0; r < 4; r++) {
        int c = tid + 128 * r;           // 0..511
        int hh = c >> 8, cc = c & 255;
        float acc = 0.f;
#pragma unroll
        for (int k = 0; k < 16; k++)
            acc = fmaf(at[hh][k], nb[k * 260 + cc], acc);
        g_wn[(size_t)b * 512 + c] = acc;
    }
}

// ============================================================
extern "C" void kernel_launch(void* const* d_in, const int* in_sizes, int n_in,
                              void* d_out, int out_size) {
    const float* center = (const float*)d_in[0];   // [B,256]
    const float* nbr    = (const float*)d_in[1];   // [B,16,256]
    const float* ew     = (const float*)d_in[2];   // [B,16]
    const float* Wc     = (const float*)d_in[3];   // [128,256]
    const float* Wn     = (const float*)d_in[4];   // [128,256]
    const float* Wv     = (const float*)d_in[5];   // [256,256]
    const float* Wo     = (const float*)d_in[6];   // [128,256]
    const float* Wco    = (const float*)d_in[7];   // [128,256]
    float* out = (float*)d_out;                    // [B,256]

    const int B = in_sizes[0] / 256;

    // K0: fold weights
    k_prep_wbig<<<(256 * 640 + 255) / 256, 256>>>(Wc, Wn, Wco);
    k_prep_mcat<<<(512 * 128 + 255) / 256, 256>>>(Wo, Wv);

    // K1: qW + center_out
    dim3 g1(B / 128, 5);
    k_sgemm<256, 640, 0><<<g1, 256>>>(center, out);

    // K2: attention -> wn
    k_attn<<<B, 128>>>(nbr, ew);

    // K3: ctx_out
    dim3 g3(B / 128, 1);
    k_sgemm<512, 128, 1><<<g3, 256>>>(nullptr, out);
}

// round 2
// speedup vs baseline: 1.0089x; 1.0089x over previous
#include <cuda_runtime.h>
#include <cstdint>

#define BMAX   131072

// ---- scratch ----
__device__ float g_wbig[256 * 640];             // K1 weight [k=256][n=640]: P0|P1|Wco^T
__device__ float g_mcatT[512 * 128];            // K3 weight [i=512][j=128]
__device__ float g_qw[(size_t)BMAX * 512];      // qW per row
__device__ float g_wn[(size_t)BMAX * 512];      // attn-weighted neighbor sums

// ============================================================
// Weight folding (tiny)
// ============================================================
__global__ void k_prep_wbig(const float* __restrict__ Wc,
                            const float* __restrict__ Wn,
                            const float* __restrict__ Wco) {
    int idx = blockIdx.x * 256 + threadIdx.x;
    if (idx >= 256 * 640) return;
    int kk = idx / 640, n = idx % 640;
    float val;
    if (n < 512) {
        int h = n >> 8, j = n & 255;
        float s = 0.f;
#pragma unroll 8
        for (int a = 0; a < 64; a++)
            s = fmaf(Wc[(h * 64 + a) * 256 + kk], Wn[(h * 64 + a) * 256 + j], s);
        val = s;
    } else {
        val = Wco[(n - 512) * 256 + kk];
    }
    g_wbig[kk * 640 + n] = val;
}

__global__ void k_prep_mcat(const float* __restrict__ Wo,
                            const float* __restrict__ Wv) {
    int idx = blockIdx.x * 256 + threadIdx.x;
    if (idx >= 512 * 128) return;
    int i = idx >> 7, j = idx & 127;
    int h = i >> 8, ii = i & 255;
    float s = 0.f;
#pragma unroll 8
    for (int d = 0; d < 128; d++)
        s = fmaf(Wo[j * 256 + h * 128 + d], Wv[(h * 128 + d) * 256 + ii], s);
    g_mcatT[i * 128 + j] = s;
}

// ============================================================
// Split-TF32 helpers
// ============================================================
__device__ __forceinline__ uint2 split_tf32(float x) {
    uint32_t hi;
    asm("cvt.rna.tf32.f32 %0, %1;" : "=r"(hi) : "f"(x));
    float r = x - __uint_as_float(hi);
    uint32_t lo;
    asm("cvt.rna.tf32.f32 %0, %1;" : "=r"(lo) : "f"(r));
    return make_uint2(hi, lo);
}

__device__ __forceinline__ void mma8(float* c,
                                     uint32_t a0, uint32_t a1, uint32_t a2, uint32_t a3,
                                     uint32_t b0, uint32_t b1) {
    asm volatile(
        "mma.sync.aligned.m16n8k8.row.col.f32.tf32.tf32.f32 "
        "{%0,%1,%2,%3},{%4,%5,%6,%7},{%8,%9},{%0,%1,%2,%3};\n"
        : "+f"(c[0]), "+f"(c[1]), "+f"(c[2]), "+f"(c[3])
        : "r"(a0), "r"(a1), "r"(a2), "r"(a3), "r"(b0), "r"(b1));
}

// ============================================================
// Tensor-core GEMM, split-tf32 (error-compensated).
// C[M,N] = A[M,KD] * B[KD,N].  Block tile 128x128, BK=16, 256 thr (8 warps, 64x32/warp).
// MODE 0: A=center, B=g_wbig (N=640). bn<4 -> g_qw, bn==4 -> out[:,0:128]
// MODE 1: A=g_wn,   B=g_mcatT (N=128) -> out[:,128:256]
// ============================================================
template <int KD, int LDB, int MODE>
__global__ __launch_bounds__(256, 2) void k_mma(const float* __restrict__ Ain,
                                                float* __restrict__ dOut) {
    __shared__ uint2 As[128][20];   // [m][k], stride 20 (16 used) -> conflict-free frag loads
    __shared__ uint2 Bs[16][132];   // [k][n], stride 132 (128 used)

    const float* A  = (MODE == 0) ? Ain : g_wn;
    const float* Bm = (MODE == 0) ? g_wbig : g_mcatT;

    const int tid = threadIdx.x;
    const int bm = blockIdx.x, bn = blockIdx.y;
    const int lane = tid & 31, w = tid >> 5;
    const int wm = (w & 1) * 64, wnn = (w >> 1) * 32;
    const int gid = lane >> 2, tg = lane & 3;

    const float* Ab = A + (size_t)bm * 128 * KD;
    const float* Bb = Bm + bn * 128;

    float acc[4][4][4];
#pragma unroll
    for (int i = 0; i < 4; i++)
#pragma unroll
        for (int j = 0; j < 4; j++)
#pragma unroll
            for (int r = 0; r < 4; r++) acc[i][j][r] = 0.f;

    for (int k0 = 0; k0 < KD; k0 += 16) {
        // A tile 128x16 -> As[m][k] split
#pragma unroll
        for (int r = 0; r < 2; r++) {
            int v = tid + 256 * r;                  // 0..511 float4s
            int row = v >> 2, c4 = v & 3;
            float4 x = *(const float4*)(Ab + (size_t)row * KD + k0 + c4 * 4);
            uint2* dst = &As[row][c4 * 4];
            dst[0] = split_tf32(x.x);
            dst[1] = split_tf32(x.y);
            dst[2] = split_tf32(x.z);
            dst[3] = split_tf32(x.w);
        }
        // B tile 16x128 -> Bs[k][n] split
#pragma unroll
        for (int r = 0; r < 2; r++) {
            int v = tid + 256 * r;
            int kk = v >> 5, c4 = v & 31;
            float4 x = *(const float4*)(Bb + (size_t)(k0 + kk) * LDB + c4 * 4);
            uint2* dst = &Bs[kk][c4 * 4];
            dst[0] = split_tf32(x.x);
            dst[1] = split_tf32(x.y);
            dst[2] = split_tf32(x.z);
            dst[3] = split_tf32(x.w);
        }
        __syncthreads();

#pragma unroll
        for (int ks = 0; ks < 2; ks++) {
            uint2 bf[4][2];
#pragma unroll
            for (int nt = 0; nt < 4; nt++) {
                int n = wnn + nt * 8 + gid;
                bf[nt][0] = Bs[ks * 8 + tg][n];
                bf[nt][1] = Bs[ks * 8 + tg + 4][n];
            }
#pragma unroll
            for (int mt = 0; mt < 4; mt++) {
                int m = wm + mt * 16 + gid;
                uint2 a0 = As[m][ks * 8 + tg];
                uint2 a1 = As[m + 8][ks * 8 + tg];
                uint2 a2 = As[m][ks * 8 + tg + 4];
                uint2 a3 = As[m + 8][ks * 8 + tg + 4];
#pragma unroll
                for (int nt = 0; nt < 4; nt++) {
                    float* c = acc[mt][nt];
                    mma8(c, a0.x, a1.x, a2.x, a3.x, bf[nt][0].x, bf[nt][1].x);  // hi*hi
                    mma8(c, a0.x, a1.x, a2.x, a3.x, bf[nt][0].y, bf[nt][1].y);  // hi*lo
                    mma8(c, a0.y, a1.y, a2.y, a3.y, bf[nt][0].x, bf[nt][1].x);  // lo*hi
                }
            }
        }
        __syncthreads();
    }

    // epilogue: float2 stores (c0,c1 adjacent cols; c2,c3 at row+8)
#pragma unroll
    for (int mt = 0; mt < 4; mt++) {
#pragma unroll
        for (int nt = 0; nt < 4; nt++) {
            const float* c = acc[mt][nt];
            int row = bm * 128 + wm + mt * 16 + gid;
            int coll = wnn + nt * 8 + 2 * tg;       // col within 128-wide block
            float2 v0 = make_float2(c[0], c[1]);
            float2 v1 = make_float2(c[2], c[3]);
            if (MODE == 0) {
                if (bn < 4) {
                    int col = bn * 128 + coll;
                    *(float2*)(g_qw + (size_t)row * 512 + col) = v0;
                    *(float2*)(g_qw + (size_t)(row + 8) * 512 + col) = v1;
                } else {
                    *(float2*)(dOut + (size_t)row * 256 + coll) = v0;
                    *(float2*)(dOut + (size_t)(row + 8) * 256 + coll) = v1;
                }
            } else {
                *(float2*)(dOut + (size_t)row * 256 + 128 + coll) = v0;
                *(float2*)(dOut + (size_t)(row + 8) * 256 + 128 + coll) = v1;
            }
        }
    }
}

// ============================================================
// K2: attention, vectorized float4 LDS throughout.
// ============================================================
__global__ __launch_bounds__(128) void k_attn(const float* __restrict__ nb_g,
                                              const float* __restrict__ ew_g) {
    const int b = blockIdx.x;
    __shared__ float nb[16 * 260];
    __shared__ float qw[512];
    __shared__ float sc[2][16];
    __shared__ float at[2][16];

    const int tid = threadIdx.x;

    const float4* src = (const float4*)(nb_g + (size_t)b * 4096);
#pragma unroll
    for (int r = 0; r < 8; r++) {
        int v = tid + 128 * r;
        int k = v >> 6, c4 = v & 63;
        float4 x = src[v];
        *(float4*)&nb[k * 260 + c4 * 4] = x;
    }
    *(float4*)&qw[tid * 4] = ((const float4*)(g_qw + (size_t)b * 512))[tid];
    __syncthreads();

    // scores: 4 threads per (h,k) dot, float4 loads
    {
        int pair = tid >> 2, sub = tid & 3;
        int h = pair >> 4, k = pair & 15;
        const float4* nr = (const float4*)&nb[k * 260 + sub * 64];
        const float4* qr = (const float4*)&qw[h * 256 + sub * 64];
        float s = 0.f;
#pragma unroll
        for (int i = 0; i < 16; i++) {
            float4 a = nr[i], q = qr[i];
            s = fmaf(a.x, q.x, s);
            s = fmaf(a.y, q.y, s);
            s = fmaf(a.z, q.z, s);
            s = fmaf(a.w, q.w, s);
        }
        s += __shfl_xor_sync(0xffffffffu, s, 1);
        s += __shfl_xor_sync(0xffffffffu, s, 2);
        if (sub == 0)
            sc[h][k] = s * 0.125f + ew_g[(size_t)b * 16 + k];
    }
    __syncthreads();

    if (tid < 32) {
        int hh = tid >> 4, kk = tid & 15;
        float v = sc[hh][kk];
        float m = v;
#pragma unroll
        for (int o = 8; o >= 1; o >>= 1)
            m = fmaxf(m, __shfl_xor_sync(0xffffffffu, m, o));
        float e = __expf(v - m);
        float sum = e;
#pragma unroll
        for (int o = 8; o >= 1; o >>= 1)
            sum += __shfl_xor_sync(0xffffffffu, sum, o);
        at[hh][kk] = e / sum;
    }
    __syncthreads();

    // wn: thread -> one float4 of the 512-wide output
    {
        int hh = tid >> 6;                 // (tid*4)>>8
        int cc = (tid * 4) & 255;
        float4 acc = make_float4(0.f, 0.f, 0.f, 0.f);
#pragma unroll
        for (int k = 0; k < 16; k++) {
            float wgt = at[hh][k];
            float4 x = *(const float4*)&nb[k * 260 + cc];
            acc.x = fmaf(wgt, x.x, acc.x);
            acc.y = fmaf(wgt, x.y, acc.y);
            acc.z = fmaf(wgt, x.z, acc.z);
            acc.w = fmaf(wgt, x.w, acc.w);
        }
        *(float4*)(g_wn + (size_t)b * 512 + tid * 4) = acc;
    }
}

// ============================================================
extern "C" void kernel_launch(void* const* d_in, const int* in_sizes, int n_in,
                              void* d_out, int out_size) {
    const float* center = (const float*)d_in[0];
    const float* nbr    = (const float*)d_in[1];
    const float* ew     = (const float*)d_in[2];
    const float* Wc     = (const float*)d_in[3];
    const float* Wn     = (const float*)d_in[4];
    const float* Wv     = (const float*)d_in[5];
    const float* Wo     = (const float*)d_in[6];
    const float* Wco    = (const float*)d_in[7];
    float* out = (float*)d_out;

    const int B = in_sizes[0] / 256;

    k_prep_wbig<<<(256 * 640 + 255) / 256, 256>>>(Wc, Wn, Wco);
    k_prep_mcat<<<(512 * 128 + 255) / 256, 256>>>(Wo, Wv);

    dim3 g1(B / 128, 5);
    k_mma<256, 640, 0><<<g1, 256>>>(center, out);

    k_attn<<<B, 128>>>(nbr, ew);

    dim3 g3(B / 128, 1);
    k_mma<512, 128, 1><<<g3, 256>>>(nullptr, out);
}

// round 4
// speedup vs baseline: 1.9559x; 1.9386x over previous
#include <cuda_runtime.h>
#include <cuda_bf16.h>
#include <cstdint>

#define BMAX 131072

// ---- scratch ----
__device__ float g_qw[(size_t)BMAX * 512];
__device__ float g_wn[(size_t)BMAX * 512];
__device__ uint4 g_b1[5 * 8 * 128 * 8];    // K1 B: 5 ntiles x 8 kh x 128 n x 8 j
__device__ uint4 g_b3[16 * 128 * 8];       // K3 B: 16 kh x 128 n x 8 j

// ============================================================
// helpers
// ============================================================
__device__ __forceinline__ uint32_t smem_u32(const void* p) {
    uint32_t a;
    asm("{ .reg .u64 t; cvta.to.shared.u64 t, %1; cvt.u32.u64 %0, t; }" : "=r"(a) : "l"(p));
    return a;
}

__device__ __forceinline__ uint32_t bpack(float a, float b) {
    __nv_bfloat16 ba = __float2bfloat16(a), bb = __float2bfloat16(b);
    return (uint32_t)__bfloat16_as_ushort(ba) |
           ((uint32_t)__bfloat16_as_ushort(bb) << 16);
}

// uint4 = { hi(v0,v1), hi(v2,v3), lo(v0,v1), lo(v2,v3) }
// (v0,v1) = k-pair kp ; (v2,v3) = k-pair kp+4
__device__ __forceinline__ uint4 mk4(float v0, float v1, float v2, float v3) {
    __nv_bfloat16 h0 = __float2bfloat16(v0), h1 = __float2bfloat16(v1);
    __nv_bfloat16 h2 = __float2bfloat16(v2), h3 = __float2bfloat16(v3);
    uint4 u;
    u.x = (uint32_t)__bfloat16_as_ushort(h0) | ((uint32_t)__bfloat16_as_ushort(h1) << 16);
    u.y = (uint32_t)__bfloat16_as_ushort(h2) | ((uint32_t)__bfloat16_as_ushort(h3) << 16);
    u.z = bpack(v0 - __bfloat162float(h0), v1 - __bfloat162float(h1));
    u.w = bpack(v2 - __bfloat162float(h2), v3 - __bfloat162float(h3));
    return u;
}

__device__ __forceinline__ void mma_bf16(float* c,
                                         uint32_t a0, uint32_t a1, uint32_t a2, uint32_t a3,
                                         uint32_t b0, uint32_t b1) {
    asm volatile(
        "mma.sync.aligned.m16n8k16.row.col.f32.bf16.bf16.f32 "
        "{%0,%1,%2,%3},{%4,%5,%6,%7},{%8,%9},{%0,%1,%2,%3};\n"
        : "+f"(c[0]), "+f"(c[1]), "+f"(c[2]), "+f"(c[3])
        : "r"(a0), "r"(a1), "r"(a2), "r"(a3), "r"(b0), "r"(b1));
}

#define CP16(dst, src) \
    asm volatile("cp.async.cg.shared.global [%0], [%1], 16;\n" :: "r"(dst), "l"(src) : "memory")
#define CPCOMMIT() asm volatile("cp.async.commit_group;\n" ::: "memory")
#define CPWAIT0()  asm volatile("cp.async.wait_group 0;\n" ::: "memory")

// ============================================================
// Prep: fold weights, split to bf16 hi/lo, pack fragment layout.
// j = ks*4+tg (0..7) -> k-pairs kp=ks*8+tg and kp+4; k = kh*32 + 2*kp (+1), +8 (+1)
// ============================================================
__global__ void k_prep_b1(const float* __restrict__ Wc, const float* __restrict__ Wn,
                          const float* __restrict__ Wco) {
    int idx = blockIdx.x * 128 + threadIdx.x;      // 40960 total
    if (idx >= 5 * 8 * 128 * 8) return;
    int j = idx & 7, n_local = (idx >> 3) & 127, kh = (idx >> 10) & 7, ntile = idx >> 13;
    int n = ntile * 128 + n_local;
    int ks = j >> 2, tg = j & 3, kp = ks * 8 + tg;
    int k0 = kh * 32 + 2 * kp;
    int k2 = k0 + 8;
    float v[4];
    int kk[4] = {k0, k0 + 1, k2, k2 + 1};
    if (n < 512) {
        int h = n >> 8, j2 = n & 255;
#pragma unroll
        for (int t = 0; t < 4; t++) {
            float s = 0.f;
#pragma unroll 8
            for (int a = 0; a < 64; a++)
                s = fmaf(Wc[(h * 64 + a) * 256 + kk[t]], Wn[(h * 64 + a) * 256 + j2], s);
            v[t] = s;
        }
    } else {
#pragma unroll
        for (int t = 0; t < 4; t++) v[t] = Wco[(n - 512) * 256 + kk[t]];
    }
    g_b1[idx] = mk4(v[0], v[1], v[2], v[3]);
}

__global__ void k_prep_b3(const float* __restrict__ Wo, const float* __restrict__ Wv) {
    int idx = blockIdx.x * 128 + threadIdx.x;      // 16384 total
    if (idx >= 16 * 128 * 8) return;
    int j = idx & 7, n = (idx >> 3) & 127, kh = idx >> 10;
    int ks = j >> 2, tg = j & 3, kp = ks * 8 + tg;
    int k0 = kh * 32 + 2 * kp;
    int kk[4] = {k0, k0 + 1, k0 + 8, k0 + 9};
    float v[4];
#pragma unroll
    for (int t = 0; t < 4; t++) {
        int k = kk[t];
        int h = k >> 8, ii = k & 255;
        float s = 0.f;
#pragma unroll 8
        for (int d = 0; d < 128; d++)
            s = fmaf(Wo[n * 256 + h * 128 + d], Wv[(h * 128 + d) * 256 + ii], s);
        v[t] = s;
    }
    g_b3[idx] = mk4(v[0], v[1], v[2], v[3]);
}

// ============================================================
// GEMM: mma.sync bf16 3-pass split. Block tile 128x128, BK=32, 256 thr.
// smem per stage: A [128][12] uint4 (24576 B) + B [128][12] uint4 -> 49152 B; 2 stages.
// MODE 0: A=center, B=g_b1 (5 ntiles): bn<4 -> g_qw, bn==4 -> out[:,0:128]
// MODE 1: A=g_wn,   B=g_b3: -> out[:,128:256]
// ============================================================
#define STAGE_BYTES 49152
#define GEMM_SMEM   (2 * STAGE_BYTES)

template <int KD, int NKH, int MODE>
__global__ __launch_bounds__(256) void k_gemm(const float* __restrict__ Ain,
                                              float* __restrict__ dOut) {
    extern __shared__ __align__(16) char smem[];
    const int tid = threadIdx.x, lid = tid & 31, w = tid >> 5;
    const int g = lid >> 2, tg = lid & 3;
    const int wm = (w & 1) * 64, wnn = (w >> 1) * 32;
    const int bn = blockIdx.x, bm = blockIdx.y;

    const float* Afp = (MODE == 0) ? Ain : g_wn;
    const uint4* Bb = ((MODE == 0) ? g_b1 : g_b3) + (size_t)bn * NKH * 1024;
    const float* Ab = Afp + (size_t)bm * 128 * KD;

    const int arow = tid >> 1, aks = tid & 1;
    const int NI = KD / 32;

#define AS_PTR(s, m, j) ((uint4*)(smem + (s) * STAGE_BYTES + ((m) * 12 + (j)) * 16))
#define BS_PTR(s, n, j) ((uint4*)(smem + (s) * STAGE_BYTES + 24576 + ((n) * 12 + (j)) * 16))

    float4 Areg[2][4];

    auto loadA = [&](int kh, int slot) {
        const float* base = Ab + (size_t)arow * KD + kh * 32 + aks * 16;
#pragma unroll
        for (int q = 0; q < 4; q++) Areg[slot][q] = *(const float4*)(base + q * 4);
    };
    auto stsA = [&](int kh, int slot) {
        int st = kh & 1;
        float4 f0 = Areg[slot][0], f1 = Areg[slot][1], f2 = Areg[slot][2], f3 = Areg[slot][3];
        *AS_PTR(st, arow, aks * 4 + 0) = mk4(f0.x, f0.y, f2.x, f2.y);
        *AS_PTR(st, arow, aks * 4 + 1) = mk4(f0.z, f0.w, f2.z, f2.w);
        *AS_PTR(st, arow, aks * 4 + 2) = mk4(f1.x, f1.y, f3.x, f3.y);
        *AS_PTR(st, arow, aks * 4 + 3) = mk4(f1.z, f1.w, f3.z, f3.w);
    };
    auto cpB = [&](int kh) {
        int st = kh & 1;
        const uint4* src = Bb + (size_t)kh * 1024;
#pragma unroll
        for (int i = 0; i < 4; i++) {
            int v = tid + 256 * i;
            int n = v >> 3, j = v & 7;
            CP16(smem_u32(BS_PTR(st, n, j)), src + v);
        }
    };

    // prologue
    cpB(0); CPCOMMIT();
    loadA(0, 0);
    stsA(0, 0);
    loadA(1, 1);
    CPWAIT0();
    __syncthreads();

    float acc[4][4][4];
#pragma unroll
    for (int i = 0; i < 4; i++)
#pragma unroll
        for (int jn = 0; jn < 4; jn++)
#pragma unroll
            for (int r = 0; r < 4; r++) acc[i][jn][r] = 0.f;

    for (int kh = 0; kh < NI; kh++) {
        const int cur = kh & 1;
        if (kh + 1 < NI) { cpB(kh + 1); CPCOMMIT(); stsA(kh + 1, (kh + 1) & 1); }
        if (kh + 2 < NI) loadA(kh + 2, kh & 1);

#pragma unroll
        for (int ks = 0; ks < 2; ks++) {
            uint4 V[4];
#pragma unroll
            for (int nt = 0; nt < 4; nt++)
                V[nt] = *BS_PTR(cur, wnn + nt * 8 + g, ks * 4 + tg);
#pragma unroll
            for (int mt = 0; mt < 4; mt++) {
                uint4 U0 = *AS_PTR(cur, wm + mt * 16 + g, ks * 4 + tg);
                uint4 U1 = *AS_PTR(cur, wm + mt * 16 + g + 8, ks * 4 + tg);
#pragma unroll
                for (int nt = 0; nt < 4; nt++) {
                    float* c = acc[mt][nt];
                    mma_bf16(c, U0.x, U1.x, U0.y, U1.y, V[nt].x, V[nt].y);  // hi*hi
                    mma_bf16(c, U0.x, U1.x, U0.y, U1.y, V[nt].z, V[nt].w);  // hi*lo
                    mma_bf16(c, U0.z, U1.z, U0.w, U1.w, V[nt].x, V[nt].y);  // lo*hi
                }
            }
        }
        if (kh + 1 < NI) CPWAIT0();
        __syncthreads();
    }

    // epilogue
#pragma unroll
    for (int mt = 0; mt < 4; mt++) {
#pragma unroll
        for (int nt = 0; nt < 4; nt++) {
            const float* c = acc[mt][nt];
            int row = bm * 128 + wm + mt * 16 + g;
            int coll = wnn + nt * 8 + 2 * tg;
            float2 v0 = make_float2(c[0], c[1]);
            float2 v1 = make_float2(c[2], c[3]);
            if (MODE == 0) {
                if (bn < 4) {
                    int col = bn * 128 + coll;
                    *(float2*)(g_qw + (size_t)row * 512 + col) = v0;
                    *(float2*)(g_qw + (size_t)(row + 8) * 512 + col) = v1;
                } else {
                    *(float2*)(dOut + (size_t)row * 256 + coll) = v0;
                    *(float2*)(dOut + (size_t)(row + 8) * 256 + coll) = v1;
                }
            } else {
                *(float2*)(dOut + (size_t)row * 256 + 128 + coll) = v0;
                *(float2*)(dOut + (size_t)(row + 8) * 256 + 128 + coll) = v1;
            }
        }
    }
#undef AS_PTR
#undef BS_PTR
}

// ============================================================
// K2: attention. Block = one b, 128 threads. Conflict-free phases.
// ============================================================
__global__ __launch_bounds__(128) void k_attn(const float* __restrict__ nb_g,
                                              const float* __restrict__ ew_g) {
    const int b = blockIdx.x;
    __shared__ float nb_s[16 * 260];
    __shared__ float qw_s[512];
    __shared__ float ews[16];
    __shared__ float sc[2][16];
    __shared__ float at[2][16];

    const int tid = threadIdx.x;
    const int k = tid >> 3, s = tid & 7;

    *(float4*)&qw_s[tid * 4] = ((const float4*)(g_qw + (size_t)b * 512))[tid];
    if (tid < 16) ews[tid] = ew_g[(size_t)b * 16 + tid];
    __syncthreads();

    // fused load + dot: thread covers nb[k], 16B chunks at lane-distinct offsets
    const float4* nb4 = (const float4*)(nb_g + (size_t)b * 4096);
    float p0 = 0.f, p1 = 0.f;
#pragma unroll
    for (int j = 0; j < 8; j++) {
        int c4 = s + 8 * j;
        float4 x = nb4[k * 64 + c4];
        *(float4*)&nb_s[k * 260 + c4 * 4] = x;
        float4 q0 = *(const float4*)&qw_s[c4 * 4];
        float4 q1 = *(const float4*)&qw_s[256 + c4 * 4];
        p0 = fmaf(x.x, q0.x, p0); p0 = fmaf(x.y, q0.y, p0);
        p0 = fmaf(x.z, q0.z, p0); p0 = fmaf(x.w, q0.w, p0);
        p1 = fmaf(x.x, q1.x, p1); p1 = fmaf(x.y, q1.y, p1);
        p1 = fmaf(x.z, q1.z, p1); p1 = fmaf(x.w, q1.w, p1);
    }
#pragma unroll
    for (int o = 1; o <= 4; o <<= 1) {
        p0 += __shfl_xor_sync(0xffffffffu, p0, o);
        p1 += __shfl_xor_sync(0xffffffffu, p1, o);
    }
    if (s == 0) {
        sc[0][k] = p0 * 0.125f + ews[k];
        sc[1][k] = p1 * 0.125f + ews[k];
    }
    __syncthreads();

    if (tid < 32) {
        int hh = tid >> 4, kk = tid & 15;
        float v = sc[hh][kk];
        float m = v;
#pragma unroll
        for (int o = 8; o >= 1; o >>= 1)
            m = fmaxf(m, __shfl_xor_sync(0xffffffffu, m, o));
        float e = __expf(v - m);
        float sum = e;
#pragma unroll
        for (int o = 8; o >= 1; o >>= 1)
            sum += __shfl_xor_sync(0xffffffffu, sum, o);
        at[hh][kk] = e / sum;
    }
    __syncthreads();

    {
        int hh = tid >> 6;
        int cc = (tid * 4) & 255;
        float4 acc = make_float4(0.f, 0.f, 0.f, 0.f);
#pragma unroll
        for (int kk = 0; kk < 16; kk++) {
            float wgt = at[hh][kk];
            float4 x = *(const float4*)&nb_s[kk * 260 + cc];
            acc.x = fmaf(wgt, x.x, acc.x);
            acc.y = fmaf(wgt, x.y, acc.y);
            acc.z = fmaf(wgt, x.z, acc.z);
            acc.w = fmaf(wgt, x.w, acc.w);
        }
        *(float4*)(g_wn + (size_t)b * 512 + tid * 4) = acc;
    }
}

// ============================================================
extern "C" void kernel_launch(void* const* d_in, const int* in_sizes, int n_in,
                              void* d_out, int out_size) {
    const float* center = (const float*)d_in[0];
    const float* nbr    = (const float*)d_in[1];
    const float* ew     = (const float*)d_in[2];
    const float* Wc     = (const float*)d_in[3];
    const float* Wn     = (const float*)d_in[4];
    const float* Wv     = (const float*)d_in[5];
    const float* Wo     = (const float*)d_in[6];
    const float* Wco    = (const float*)d_in[7];
    float* out = (float*)d_out;

    const int B = in_sizes[0] / 256;

    cudaFuncSetAttribute(k_gemm<256, 8, 0>, cudaFuncAttributeMaxDynamicSharedMemorySize, GEMM_SMEM);
    cudaFuncSetAttribute(k_gemm<512, 16, 1>, cudaFuncAttributeMaxDynamicSharedMemorySize, GEMM_SMEM);

    k_prep_b1<<<320, 128>>>(Wc, Wn, Wco);
    k_prep_b3<<<128, 128>>>(Wo, Wv);

    k_gemm<256, 8, 0><<<dim3(5, B / 128), 256, GEMM_SMEM>>>(center, out);
    k_attn<<<B, 128>>>(nbr, ew);
    k_gemm<512, 16, 1><<<dim3(1, B / 128), 256, GEMM_SMEM>>>(nullptr, out);
}